// round 1
// baseline (speedup 1.0000x reference)
#include <cuda_runtime.h>
#include <cuda_bf16.h>
#include <math.h>

// Problem constants
#define NB   128
#define NS   2048
#define NM   50
#define NDK  64
#define NDV  128
#define NK   5
#define NDS  50
#define NQ   1001
#define NPOS (NB*NS)   // 262144

// -------- scratch (__device__ globals; no runtime allocation) --------
__device__ float g_attn [NQ * 64];            // softmax(q_e @ key_mem^T), padded stride 64
__device__ float g_sumq [NQ * 64];            // q_e @ summary_w[128:192], padded stride 64
__device__ float g_alpha[NQ];
__device__ float g_beta [NQ * 4];
__device__ float g_erase[NQ * NK * NDV];      // sigmoid(ve @ erase_w + b)
__device__ float g_add  [NQ * NK * NDV];      // tanh(ve @ add_w + b)
__device__ float g_reads[(long)NB * NS * NDV];// 134 MB

// ======================= Phase A1: per-question tables =======================
__global__ void build_q_tables(const float* __restrict__ qe_w,
                               const float* __restrict__ key_mem,
                               const float* __restrict__ sum_w,
                               const float* __restrict__ alpha_w,
                               const float* __restrict__ alpha_b,
                               const float* __restrict__ beta_w,
                               const float* __restrict__ beta_b) {
    int q = blockIdx.x;
    int tid = threadIdx.x;           // 64 threads
    __shared__ float qe[64];
    __shared__ float lg[NM];
    qe[tid] = qe_w[q * 64 + tid];
    __syncthreads();

    if (tid < NM) {
        float a = 0.f, s = 0.f;
        #pragma unroll
        for (int k = 0; k < 64; k++) {
            float qk = qe[k];
            a = fmaf(qk, key_mem[tid * 64 + k], a);
            s = fmaf(qk, sum_w[(128 + k) * NDS + tid], s);
        }
        lg[tid] = a;
        g_sumq[q * 64 + tid] = s;
    }
    __syncthreads();

    if (tid < NM) {
        float mx = -1e30f;
        for (int m = 0; m < NM; m++) mx = fmaxf(mx, lg[m]);
        float den = 0.f;
        for (int m = 0; m < NM; m++) den += expf(lg[m] - mx);
        g_attn[q * 64 + tid] = expf(lg[tid] - mx) / den;
    }
    if (tid == 0) {
        float x = alpha_b[0];
        #pragma unroll
        for (int k = 0; k < 64; k++) x = fmaf(qe[k], alpha_w[k], x);
        // stable softplus
        g_alpha[q] = fmaxf(x, 0.f) + log1pf(expf(-fabsf(x)));
    }
    if (tid >= 1 && tid < 5) {
        int t = tid - 1;
        float x = beta_b[t];
        #pragma unroll
        for (int k = 0; k < 64; k++) x = fmaf(qe[k], beta_w[k * 4 + t], x);
        g_beta[q * 4 + t] = x;
    }
}

// ================= Phase A2: per-(question,response) erase/add =================
__global__ __launch_bounds__(128)
void build_qr_tables(const float* __restrict__ item_w,
                     const float* __restrict__ vp_w,
                     const float* __restrict__ vp_b,
                     const float* __restrict__ er_w,
                     const float* __restrict__ er_b,
                     const float* __restrict__ ad_w,
                     const float* __restrict__ ad_b) {
    int q = blockIdx.x;
    int v = threadIdx.x;             // 128 threads, v = DV index (and later j)
    __shared__ float iv[64];
    __shared__ float veS[NK][NDV];

    if (v < 64) iv[v] = item_w[q * 64 + v];
    __syncthreads();

    // value_embed for all 5 responses
    float common = vp_b[v];
    #pragma unroll
    for (int i = 0; i < 64; i++) common = fmaf(iv[i], vp_w[i * NDV + v], common);
    #pragma unroll
    for (int r = 0; r < NK; r++) {
        float x = common;
        #pragma unroll
        for (int k = 0; k < NK; k++) {
            float rf = fmaxf(0.f, 1.f - fabsf((float)k - (float)r) * 0.25f);
            x = fmaf(rf, vp_w[(64 + k) * NDV + v], x);
        }
        veS[r][v] = x;
    }
    __syncthreads();

    int j = v;
    float eacc[NK], aacc[NK];
    #pragma unroll
    for (int r = 0; r < NK; r++) { eacc[r] = er_b[j]; aacc[r] = ad_b[j]; }
    for (int v2 = 0; v2 < NDV; v2++) {
        float we = er_w[v2 * NDV + j];
        float wa = ad_w[v2 * NDV + j];
        #pragma unroll
        for (int r = 0; r < NK; r++) {
            float t = veS[r][v2];
            eacc[r] = fmaf(t, we, eacc[r]);
            aacc[r] = fmaf(t, wa, aacc[r]);
        }
    }
    #pragma unroll
    for (int r = 0; r < NK; r++) {
        long base = ((long)q * NK + r) * NDV + j;
        g_erase[base] = 1.f / (1.f + expf(-eacc[r]));
        g_add  [base] = tanhf(aacc[r]);
    }
}

// ========================= Phase B: sequential scan =========================
// One CTA per batch element. Thread d owns memory column d; 50 state values in
// registers. attn via double-buffered smem; erase/add prefetched 1 step ahead.
__global__ __launch_bounds__(128, 1)
void scan_kernel(const int* __restrict__ questions,
                 const int* __restrict__ responses,
                 const float* __restrict__ init_mem) {
    int b = blockIdx.x;
    int d = threadIdx.x;
    __shared__ int   qsh[NS];
    __shared__ int   rsh[NS];
    __shared__ float attnS[2][NM];

    for (int i = d; i < NS; i += 128) {
        qsh[i] = questions[b * NS + i];
        rsh[i] = responses[b * NS + i];
    }

    float mem[NM];
    #pragma unroll
    for (int m = 0; m < NM; m++) mem[m] = init_mem[m * NDV + d];

    __syncthreads();

    int q0 = qsh[0], r0 = rsh[0];
    long base0 = ((long)q0 * NK + r0) * NDV;
    float e_cur = g_erase[base0 + d];
    float a_cur = g_add  [base0 + d];
    if (d < NM) attnS[0][d] = g_attn[q0 * 64 + d];
    __syncthreads();

    int buf = 0;
    float* outp = g_reads + ((long)b * NS) * NDV + d;

    for (int t = 0; t < NS; t++) {
        // prefetch step t+1
        float e_nxt = e_cur, a_nxt = a_cur, an_reg = 0.f;
        bool have = (t + 1 < NS);
        if (have) {
            int qn = qsh[t + 1], rn = rsh[t + 1];
            long baseN = ((long)qn * NK + rn) * NDV;
            e_nxt = g_erase[baseN + d];
            a_nxt = g_add  [baseN + d];
            if (d < NM) an_reg = g_attn[qn * 64 + d];
        }

        // read (uses mem BEFORE update) fused with update
        float racc[4] = {0.f, 0.f, 0.f, 0.f};
        #pragma unroll
        for (int m = 0; m < NM; m++) {
            float w = attnS[buf][m];
            racc[m & 3] = fmaf(w, mem[m], racc[m & 3]);
            float x = fmaf(-mem[m], e_cur, a_cur);   // add - mem*erase
            mem[m] = fmaf(w, x, mem[m]);             // mem*(1-w*e) + w*a
        }
        outp[(long)t * NDV] = (racc[0] + racc[1]) + (racc[2] + racc[3]);

        if (have && d < NM) attnS[buf ^ 1][d] = an_reg;
        e_cur = e_nxt;
        a_cur = a_nxt;
        __syncthreads();
        buf ^= 1;
    }
}

// ===================== Phase C: summary / outputs =====================
// Tile of 32 positions per block; smem GEMM read[32x128] @ W[128x52(pad 50)].
// Then per-position tail: theta, alpha, beta, logits, probs.
#define CT 32
__global__ __launch_bounds__(128)
void output_kernel(const int* __restrict__ questions,
                   const float* __restrict__ sum_w,    // (192,50); rows 0..127 used
                   const float* __restrict__ sum_b,
                   const float* __restrict__ theta_w,
                   const float* __restrict__ theta_b,
                   float* __restrict__ out) {
    __shared__ float rS[CT * 128];   // reads tile; reused as summary tile (32x52)
    __shared__ float wS[128 * 52];
    __shared__ float twS[52];

    int tid = threadIdx.x;
    long p0 = (long)blockIdx.x * CT;

    for (int i = tid; i < 128 * 52; i += 128) {
        int dd = i / 52, j = i % 52;
        wS[i] = (j < NDS) ? sum_w[dd * NDS + j] : 0.f;
    }
    if (tid < 52) twS[tid] = (tid < NDS) ? theta_w[tid] : 0.f;
    for (int i = tid; i < CT * 128; i += 128) rS[i] = g_reads[p0 * 128 + i];
    __syncthreads();

    // 8 pos-groups x 13 j-groups = 104 active threads; 4 pos x 4 j each
    int pg = tid / 13;
    int jg = tid - pg * 13;
    bool active = (tid < 104);
    float acc[4][4];
    int pbase = pg * 4, jbase = jg * 4;
    if (active) {
        #pragma unroll
        for (int a = 0; a < 4; a++)
            #pragma unroll
            for (int b2 = 0; b2 < 4; b2++) acc[a][b2] = 0.f;
        for (int dd = 0; dd < 128; dd++) {
            const float4 wv = *(const float4*)&wS[dd * 52 + jbase];
            #pragma unroll
            for (int pp = 0; pp < 4; pp++) {
                float rv = rS[(pbase + pp) * 128 + dd];
                acc[pp][0] = fmaf(rv, wv.x, acc[pp][0]);
                acc[pp][1] = fmaf(rv, wv.y, acc[pp][1]);
                acc[pp][2] = fmaf(rv, wv.z, acc[pp][2]);
                acc[pp][3] = fmaf(rv, wv.w, acc[pp][3]);
            }
        }
    }
    __syncthreads();   // all reads of rS done; now reuse as summary tile

    if (active) {
        #pragma unroll
        for (int pp = 0; pp < 4; pp++) {
            int pos = pbase + pp;
            long p = p0 + pos;
            int q = questions[p];
            #pragma unroll
            for (int jj = 0; jj < 4; jj++) {
                int j = jbase + jj;
                float s = 0.f;
                if (j < NDS)
                    s = tanhf(acc[pp][jj] + g_sumq[q * 64 + j] + sum_b[j]);
                rS[pos * 52 + j] = s;
            }
        }
    }
    __syncthreads();

    if (tid < CT) {
        long p = p0 + tid;
        int q = questions[p];
        float th = theta_b[0];
        #pragma unroll
        for (int j = 0; j < NDS; j++) th = fmaf(rS[tid * 52 + j], twS[j], th);
        th = tanhf(th);
        float al = g_alpha[q];
        float inter = th * al;
        float bt[4];
        #pragma unroll
        for (int t = 0; t < 4; t++) bt[t] = g_beta[q * 4 + t];
        float lg[5];
        lg[0] = 0.f;
        float c = 0.f;
        #pragma unroll
        for (int t = 0; t < 4; t++) { c += inter - bt[t]; lg[t + 1] = c; }
        float mx = lg[0];
        #pragma unroll
        for (int i = 1; i < 5; i++) mx = fmaxf(mx, lg[i]);
        float ex[5], den = 0.f;
        #pragma unroll
        for (int i = 0; i < 5; i++) { ex[i] = expf(lg[i] - mx); den += ex[i]; }
        float inv = 1.f / den;

        const long NBS = (long)NPOS;
        out[p]               = th;           // theta
        out[NBS + p]         = al;           // alpha
        #pragma unroll
        for (int t = 0; t < 4; t++) out[2 * NBS + p * 4 + t] = bt[t];   // beta
        #pragma unroll
        for (int i = 0; i < 5; i++) out[6 * NBS + p * 5 + i] = lg[i];   // logits
        #pragma unroll
        for (int i = 0; i < 5; i++) out[11 * NBS + p * 5 + i] = ex[i] * inv; // probs
    }
}

// ============================== launcher ==============================
extern "C" void kernel_launch(void* const* d_in, const int* in_sizes, int n_in,
                              void* d_out, int out_size) {
    const int*   questions    = (const int*)  d_in[0];
    const int*   responses    = (const int*)  d_in[1];
    const float* q_embed_w    = (const float*)d_in[2];
    const float* item_embed_w = (const float*)d_in[3];
    const float* value_proj_w = (const float*)d_in[4];
    const float* value_proj_b = (const float*)d_in[5];
    const float* key_mem      = (const float*)d_in[6];
    const float* init_mem     = (const float*)d_in[7];
    const float* erase_w      = (const float*)d_in[8];
    const float* erase_b      = (const float*)d_in[9];
    const float* add_w        = (const float*)d_in[10];
    const float* add_b        = (const float*)d_in[11];
    const float* summary_w    = (const float*)d_in[12];
    const float* summary_b    = (const float*)d_in[13];
    const float* theta_w      = (const float*)d_in[14];
    const float* theta_b      = (const float*)d_in[15];
    const float* alpha_w      = (const float*)d_in[16];
    const float* alpha_b      = (const float*)d_in[17];
    const float* beta_w       = (const float*)d_in[18];
    const float* beta_b       = (const float*)d_in[19];
    float* out = (float*)d_out;

    build_q_tables<<<NQ, 64>>>(q_embed_w, key_mem, summary_w,
                               alpha_w, alpha_b, beta_w, beta_b);
    build_qr_tables<<<NQ, 128>>>(item_embed_w, value_proj_w, value_proj_b,
                                 erase_w, erase_b, add_w, add_b);
    scan_kernel<<<NB, 128>>>(questions, responses, init_mem);
    output_kernel<<<NPOS / CT, 128>>>(questions, summary_w, summary_b,
                                      theta_w, theta_b, out);
}